// round 13
// baseline (speedup 1.0000x reference)
#include <cuda_runtime.h>
#include <cstdint>

// Fused y = conv3x3_same(x, w1); z = conv3x3_same(y, w2), [16,1,2048,2048] fp32.
// Warp = 256-col strip x 64-row chunk, 8 cols/lane. X rows stream through a
// warp-private 6-slot cp.async smem ring. The pipelined row crosses the step
// boundary as RAW smem words + shuffled halo (12 regs) and is packed at use.
// y-halo shuffles issued early (hidden under addY FMAs). Incremental
// accumulation + packed f32x2 FMAs. 5 CTAs/SM target (102 regs).
// y forced to 0 outside the image (exact two-pass SAME semantics).

#define IMG_H 2048
#define IMG_W 2048
#define ROWS 64
#define STRIPS 8
#define WARPS_PER_CTA 4
#define RING 6
#define ROWB 1088                  // 8 pad + 256 data + 8 pad floats
#define WSMEM (RING * ROWB)

typedef unsigned long long u64;

__device__ __forceinline__ u64 pk(float lo, float hi) {
    u64 r; asm("mov.b64 %0, {%1, %2};" : "=l"(r) : "f"(lo), "f"(hi)); return r;
}
__device__ __forceinline__ float lo32(u64 v) { return __uint_as_float((unsigned)v); }
__device__ __forceinline__ float hi32(u64 v) { return __uint_as_float((unsigned)(v >> 32)); }
__device__ __forceinline__ u64 fma2(u64 a, u64 b, u64 c) {
    u64 d; asm("fma.rn.f32x2 %0, %1, %2, %3;" : "=l"(d) : "l"(a), "l"(b), "l"(c)); return d;
}
__device__ __forceinline__ u64 mul2(u64 a, u64 b) {
    u64 d; asm("mul.rn.f32x2 %0, %1, %2;" : "=l"(d) : "l"(a), "l"(b)); return d;
}
__device__ __forceinline__ void cpa16(uint32_t d, const float* s) {
    asm volatile("cp.async.cg.shared.global [%0], [%1], 16;" :: "r"(d), "l"(s));
}
__device__ __forceinline__ void cpa8(uint32_t d, const float* s) {
    asm volatile("cp.async.ca.shared.global [%0], [%1], 8;" :: "r"(d), "l"(s));
}

struct RW { u64 a0, a1, b0, b1; float xm1, xp8, h0, h1; };  // raw row state
struct XP { u64 P[9]; float ea, eb, ec; };
struct YA { u64 a[4]; float ae; };
struct YQ { u64 Q[9]; };
struct ZA { u64 a[4]; };

template <bool SAFE>
__device__ __forceinline__ void issue_row(char* slot, uint32_t slot_u,
                                          const float* src, int lane,
                                          bool lE, bool rE, bool inimg)
{
    if (SAFE || inimg) {
        uint32_t d = slot_u + 32 + lane * 32;
        cpa16(d,      src + 8 * lane);
        cpa16(d + 16, src + 8 * lane + 4);
        if (lane == 0  && !lE) cpa8(slot_u + 24,   src - 2);
        if (lane == 31 && !rE) cpa8(slot_u + 1056, src + 256);
    } else {
        float4 z4 = make_float4(0.f, 0.f, 0.f, 0.f);
        *(float4*)(slot + 32 + lane * 32) = z4;
        *(float4*)(slot + 48 + lane * 32) = z4;
        if (lane == 0)  *(float2*)(slot + 24)   = make_float2(0.f, 0.f);
        if (lane == 31) *(float2*)(slot + 1056) = make_float2(0.f, 0.f);
    }
}

// Read a ready slot: 2x LDS.128 + halo float2; do halo shuffles immediately.
__device__ __forceinline__ RW ldraw(const char* slot, int lane)
{
    const float* sf = (const float*)slot;
    const ulonglong2* dp = (const ulonglong2*)(sf + 8 + lane * 8);
    ulonglong2 A = dp[0], B = dp[1];
    float2 h = *(const float2*)(sf + ((lane == 31) ? 264 : 6));
    RW r;
    r.a0 = A.x; r.a1 = A.y; r.b0 = B.x; r.b1 = B.y;
    float up = __shfl_up_sync(0xffffffffu, hi32(B.y), 1);
    float dn = __shfl_down_sync(0xffffffffu, lo32(A.x), 1);
    r.xm1 = (lane == 0)  ? h.y : up;
    r.xp8 = (lane == 31) ? h.x : dn;
    r.h0 = h.x; r.h1 = h.y;
    return r;
}

// Pack raw row into shifted f32x2 pairs (aligned pairs are the raw u64s).
__device__ __forceinline__ XP packx(const RW& p, int lane)
{
    float v0 = lo32(p.a0), v1 = hi32(p.a0), v2 = lo32(p.a1), v3 = hi32(p.a1);
    float v4 = lo32(p.b0), v5 = hi32(p.b0), v6 = lo32(p.b1), v7 = hi32(p.b1);
    XP x;
    x.P[0] = pk(p.xm1, v0);
    x.P[1] = p.a0;
    x.P[2] = pk(v1, v2);
    x.P[3] = p.a1;
    x.P[4] = pk(v3, v4);
    x.P[5] = p.b0;
    x.P[6] = pk(v5, v6);
    x.P[7] = p.b1;
    x.P[8] = pk(v7, p.xp8);
    x.ea = (lane == 0) ? p.h0  : v7;
    x.eb = (lane == 0) ? p.xm1 : p.xp8;
    x.ec = (lane == 0) ? v0    : p.h1;
    return x;
}

template <int A, bool FIRST>
__device__ __forceinline__ void addY(YA& y, const XP& x, const u64* W)
{
#pragma unroll
    for (int j = 0; j < 4; j++) {
        u64 t = FIRST ? mul2(W[3*A], x.P[2*j])
                      : fma2(W[3*A], x.P[2*j], y.a[j]);
        t = fma2(W[3*A+1], x.P[2*j+1], t);
        y.a[j] = fma2(W[3*A+2], x.P[2*j+2], t);
    }
    float e = FIRST ? (lo32(W[3*A]) * x.ea)
                    : fmaf(lo32(W[3*A]), x.ea, y.ae);
    e = fmaf(lo32(W[3*A+1]), x.eb, e);
    y.ae = fmaf(lo32(W[3*A+2]), x.ec, e);
}

// finB: build packed y pairs from masked YA + precomputed halo shuffles.
__device__ __forceinline__ YQ finB(const YA& y, float fup, float fdn, int lane)
{
    float y0 = lo32(y.a[0]), y7 = hi32(y.a[3]);
    float ym1 = (lane == 0)  ? y.ae : fup;
    float yp8 = (lane == 31) ? y.ae : fdn;
    YQ q;
    q.Q[0] = pk(ym1, y0);
#pragma unroll
    for (int j = 0; j < 4; j++) q.Q[2*j+1] = y.a[j];
#pragma unroll
    for (int j = 1; j < 4; j++) q.Q[2*j] = pk(hi32(y.a[j-1]), lo32(y.a[j]));
    q.Q[8] = pk(y7, yp8);
    return q;
}

// full fin (prologue only)
template <bool SAFE>
__device__ __forceinline__ YQ fin(YA y, bool valid, bool killE, int lane)
{
    if (!SAFE && !valid) {
#pragma unroll
        for (int j = 0; j < 4; j++) y.a[j] = 0ull;
        y.ae = 0.f;
    }
    if (killE) y.ae = 0.f;
    float fup = __shfl_up_sync(0xffffffffu, hi32(y.a[3]), 1);
    float fdn = __shfl_down_sync(0xffffffffu, lo32(y.a[0]), 1);
    return finB(y, fup, fdn, lane);
}

template <int A, bool FIRST>
__device__ __forceinline__ void addZ(ZA& z, const YQ& q, const u64* W)
{
#pragma unroll
    for (int j = 0; j < 4; j++) {
        u64 t = FIRST ? mul2(W[3*A], q.Q[2*j])
                      : fma2(W[3*A], q.Q[2*j], z.a[j]);
        t = fma2(W[3*A+1], q.Q[2*j+1], t);
        z.a[j] = fma2(W[3*A+2], q.Q[2*j+2], t);
    }
}

__device__ __forceinline__ void stz(float* p, const ZA& z)
{
    *(float4*)p       = make_float4(lo32(z.a[0]), hi32(z.a[0]),
                                    lo32(z.a[1]), hi32(z.a[1]));
    *(float4*)(p + 4) = make_float4(lo32(z.a[2]), hi32(z.a[2]),
                                    lo32(z.a[3]), hi32(z.a[3]));
}

template <bool SAFE>
__device__ __forceinline__ void run(char* wb, uint32_t wb_u,
                                    const float* __restrict__ xb,
                                    float* __restrict__ ob,
                                    const float* __restrict__ w1g,
                                    const float* __restrict__ w2g,
                                    int c0, int R0, int lane, bool lE, bool rE)
{
    u64 W1[9], W2[9];
#pragma unroll
    for (int i = 0; i < 9; i++) {
        float a = __ldg(w1g + i); W1[i] = pk(a, a);
        float b = __ldg(w2g + i); W2[i] = pk(b, b);
    }
    const bool killE = (lane == 0 && lE) || (lane == 31 && rE);

    // Zero halo pads once (read only by the lane that zeroes them).
    if (lane == 0) {
#pragma unroll
        for (int s = 0; s < RING; s++)
            *(float2*)(wb + s * ROWB + 24) = make_float2(0.f, 0.f);
    }
    if (lane == 31) {
#pragma unroll
        for (int s = 0; s < RING; s++)
            *(float2*)(wb + s * ROWB + 1056) = make_float2(0.f, 0.f);
    }

    // ---- Prologue: issue rows R0-2 .. R0+2 into slots 0..4 ----
    const float* srcp = xb + (size_t)(R0 - 2) * IMG_W + c0;
    int irow = R0 - 2;
    const int RLAST = R0 + 65;
#pragma unroll
    for (int s = 0; s < 5; s++) {
        issue_row<SAFE>(wb + s * ROWB, wb_u + s * ROWB, srcp, lane, lE, rE,
                        (unsigned)irow < IMG_H);
        asm volatile("cp.async.commit_group;");
        srcp += IMG_W; irow++;
    }

    int coff = 0;
    float* orow = ob + (size_t)R0 * IMG_W + c0 + 8 * lane;
    int r = R0;
    RW Rw;

#define CONSUME_RAW()                                                         \
    do {                                                                      \
        asm volatile("cp.async.wait_group 4;");                               \
        Rw = ldraw(wb + coff, lane);                                          \
        int io_ = coff + 5 * ROWB; if (io_ >= WSMEM) io_ -= WSMEM;            \
        coff += ROWB; if (coff == WSMEM) coff = 0;                            \
        if (irow <= RLAST) {                                                  \
            issue_row<SAFE>(wb + io_, wb_u + io_, srcp, lane, lE, rE,         \
                            (unsigned)irow < IMG_H);                          \
            srcp += IMG_W; irow++;                                            \
        }                                                                     \
        asm volatile("cp.async.commit_group;");                               \
    } while (0)

    YA t1, t2, ya, yb, yc;
    ZA za, zb, zc;

    CONSUME_RAW();                                     // row R0-2
    { XP A = packx(Rw, lane); addY<0, true >(t1, A, W1); }
    CONSUME_RAW();                                     // row R0-1
    { XP B = packx(Rw, lane);
      addY<1, false>(t1, B, W1); addY<0, true >(t2, B, W1); }
    CONSUME_RAW();                                     // row R0
    { XP C = packx(Rw, lane);
      addY<2, false>(t1, C, W1); addY<1, false>(t2, C, W1);
      addY<0, true >(ya, C, W1); }
    { YQ Q = fin<SAFE>(t1, (unsigned)(R0 - 1) < IMG_H, killE, lane);
      addZ<0, true >(za, Q, W2); }
    CONSUME_RAW();                                     // row R0+1
    { XP D = packx(Rw, lane);
      addY<2, false>(t2, D, W1); addY<1, false>(ya, D, W1);
      addY<0, true >(yb, D, W1); }
    { YQ Q = fin<SAFE>(t2, true, killE, lane);
      addZ<1, false>(za, Q, W2); addZ<0, true >(zb, Q, W2); }
    CONSUME_RAW();                                     // row R0+2 (primes Rw)

    // ---- Steady state: Rw = raw row r+2. Pack, addY, early y-shuffles,
    //      consume row r+3 (LDS hidden), finish z(r), store. ----
#define STEP_CORE(Y0, Y1, Y2, Z0, Z1, Z2, DO_CONSUME)                         \
    do {                                                                      \
        XP X = packx(Rw, lane);                                               \
        addY<2, false>(Y0, X, W1);                                            \
        if (!SAFE && !((unsigned)(r + 1) < IMG_H)) {                          \
            Y0.a[0] = 0ull; Y0.a[1] = 0ull; Y0.a[2] = 0ull; Y0.a[3] = 0ull;   \
            Y0.ae = 0.f;                                                      \
        }                                                                     \
        if (killE) Y0.ae = 0.f;                                               \
        float fup = __shfl_up_sync(0xffffffffu, hi32(Y0.a[3]), 1);            \
        float fdn = __shfl_down_sync(0xffffffffu, lo32(Y0.a[0]), 1);          \
        addY<1, false>(Y1, X, W1);                                            \
        addY<0, true >(Y2, X, W1);                                            \
        if (DO_CONSUME) CONSUME_RAW();                                        \
        YQ Qs = finB(Y0, fup, fdn, lane);                                     \
        addZ<2, false>(Z0, Qs, W2);                                           \
        addZ<1, false>(Z1, Qs, W2);                                           \
        addZ<0, true >(Z2, Qs, W2);                                           \
        stz(orow, Z0);                                                        \
        orow += IMG_W; r++;                                                   \
    } while (0)

#pragma unroll 1
    for (int i = 0; i < 21; i++) {                     // 63 rows
        STEP_CORE(ya, yb, yc, za, zb, zc, true);
        STEP_CORE(yb, yc, ya, zb, zc, za, true);
        STEP_CORE(yc, ya, yb, zc, za, zb, true);
    }
    STEP_CORE(ya, yb, yc, za, zb, zc, false);          // row 64 (Rw already held)
#undef STEP_CORE
#undef CONSUME_RAW
}

__global__ __launch_bounds__(WARPS_PER_CTA * 32, 5)
void conv2x_ring3(const float* __restrict__ x, const float* __restrict__ w1g,
                  const float* __restrict__ w2g, float* __restrict__ out)
{
    __shared__ __align__(16) char smem[WARPS_PER_CTA * WSMEM];   // 26112 B

    const int lane  = threadIdx.x & 31;
    const int wrp   = threadIdx.x >> 5;
    const int strip = blockIdx.x;                       // 0..7
    const int chunk = blockIdx.y * WARPS_PER_CTA + wrp; // 0..31
    const int c0 = strip * 256;
    const int R0 = chunk * ROWS;
    const bool lE = (strip == 0);
    const bool rE = (strip == STRIPS - 1);

    char* wb = smem + wrp * WSMEM;
    uint32_t wb_u = (uint32_t)__cvta_generic_to_shared(wb);

    const float* xb = x   + (size_t)blockIdx.z * ((size_t)IMG_H * IMG_W);
    float*       ob = out + (size_t)blockIdx.z * ((size_t)IMG_H * IMG_W);

    if (chunk != 0 && chunk != (IMG_H / ROWS) - 1)
        run<true >(wb, wb_u, xb, ob, w1g, w2g, c0, R0, lane, lE, rE);
    else
        run<false>(wb, wb_u, xb, ob, w1g, w2g, c0, R0, lane, lE, rE);
}

extern "C" void kernel_launch(void* const* d_in, const int* in_sizes, int n_in,
                              void* d_out, int out_size)
{
    const float* x  = (const float*)d_in[0];
    const float* w1 = (const float*)d_in[1];
    const float* w2 = (const float*)d_in[2];
    float* out = (float*)d_out;

    cudaFuncSetAttribute(conv2x_ring3,
                         cudaFuncAttributePreferredSharedMemoryCarveout, 100);

    const int B = in_sizes[0] / (IMG_H * IMG_W);            // 16
    dim3 grid(STRIPS, (IMG_H / ROWS) / WARPS_PER_CTA, B);   // 8 x 8 x 16 = 1024
    conv2x_ring3<<<grid, WARPS_PER_CTA * 32>>>(x, w1, w2, out);
}

// round 14
// speedup vs baseline: 1.5626x; 1.5626x over previous
#include <cuda_runtime.h>
#include <cstdint>

// Fused y = conv3x3_same(x, w1); z = conv3x3_same(y, w2), [16,1,2048,2048] fp32.
// Round-12 structure (best: 104.3us) with a deeper prefetch ring: 8 slots,
// wait_group 6 -> 7 rows in flight per warp. Warp = 256-col strip x 64-row
// chunk, 8 cols/lane, warp-private cp.async smem ring, ulonglong2 readback,
// shuffle halo, LDS of row r+3 overlapped with fin/addZ of z(r).
// Incremental accumulation + packed f32x2 FMAs. y forced to 0 outside image.

#define IMG_H 2048
#define IMG_W 2048
#define ROWS 64
#define STRIPS 8
#define WARPS_PER_CTA 4
#define RING 8
#define ROWB 1088                  // 8 pad + 256 data + 8 pad floats
#define WSMEM (RING * ROWB)        // 8704 B per warp

typedef unsigned long long u64;

__device__ __forceinline__ u64 pk(float lo, float hi) {
    u64 r; asm("mov.b64 %0, {%1, %2};" : "=l"(r) : "f"(lo), "f"(hi)); return r;
}
__device__ __forceinline__ float lo32(u64 v) { return __uint_as_float((unsigned)v); }
__device__ __forceinline__ float hi32(u64 v) { return __uint_as_float((unsigned)(v >> 32)); }
__device__ __forceinline__ u64 fma2(u64 a, u64 b, u64 c) {
    u64 d; asm("fma.rn.f32x2 %0, %1, %2, %3;" : "=l"(d) : "l"(a), "l"(b), "l"(c)); return d;
}
__device__ __forceinline__ u64 mul2(u64 a, u64 b) {
    u64 d; asm("mul.rn.f32x2 %0, %1, %2;" : "=l"(d) : "l"(a), "l"(b)); return d;
}
__device__ __forceinline__ void cpa16(uint32_t d, const float* s) {
    asm volatile("cp.async.cg.shared.global [%0], [%1], 16;" :: "r"(d), "l"(s));
}
__device__ __forceinline__ void cpa8(uint32_t d, const float* s) {
    asm volatile("cp.async.ca.shared.global [%0], [%1], 8;" :: "r"(d), "l"(s));
}

struct XP { u64 P[9]; float ea, eb, ec; };
struct YA { u64 a[4]; float ae; };
struct YQ { u64 Q[9]; };
struct ZA { u64 a[4]; };

template <bool SAFE>
__device__ __forceinline__ void issue_row(char* slot, uint32_t slot_u,
                                          const float* src, int lane,
                                          bool lE, bool rE, bool inimg)
{
    if (SAFE || inimg) {
        uint32_t d = slot_u + 32 + lane * 32;
        cpa16(d,      src + 8 * lane);
        cpa16(d + 16, src + 8 * lane + 4);
        if (lane == 0  && !lE) cpa8(slot_u + 24,   src - 2);     // x[-2],x[-1]
        if (lane == 31 && !rE) cpa8(slot_u + 1056, src + 256);   // x[256],x[257]
    } else {
        float4 z4 = make_float4(0.f, 0.f, 0.f, 0.f);
        *(float4*)(slot + 32 + lane * 32) = z4;
        *(float4*)(slot + 48 + lane * 32) = z4;
        if (lane == 0)  *(float2*)(slot + 24)   = make_float2(0.f, 0.f);
        if (lane == 31) *(float2*)(slot + 1056) = make_float2(0.f, 0.f);
    }
}

// Read a ready slot: 2x LDS.128 as ulonglong2 (aligned pairs free) + own halo.
__device__ __forceinline__ XP cvts(const char* slot, int lane)
{
    const float* sf = (const float*)slot;
    const ulonglong2* dp = (const ulonglong2*)(sf + 8 + lane * 8);
    ulonglong2 A = dp[0], B = dp[1];
    float2 h = *(const float2*)(sf + ((lane == 31) ? 264 : 6));  // used by 0/31 only
    float v0 = lo32(A.x), v1 = hi32(A.x), v2 = lo32(A.y), v3 = hi32(A.y);
    float v4 = lo32(B.x), v5 = hi32(B.x), v6 = lo32(B.y), v7 = hi32(B.y);
    float up = __shfl_up_sync(0xffffffffu, v7, 1);
    float dn = __shfl_down_sync(0xffffffffu, v0, 1);
    float xm1 = (lane == 0)  ? h.y : up;
    float xp8 = (lane == 31) ? h.x : dn;
    XP x;
    x.P[0] = pk(xm1, v0);
    x.P[1] = A.x;
    x.P[2] = pk(v1, v2);
    x.P[3] = A.y;
    x.P[4] = pk(v3, v4);
    x.P[5] = B.x;
    x.P[6] = pk(v5, v6);
    x.P[7] = B.y;
    x.P[8] = pk(v7, xp8);
    x.ea = (lane == 0) ? h.x : v7;
    x.eb = (lane == 0) ? xm1 : xp8;
    x.ec = (lane == 0) ? v0  : h.y;
    return x;
}

template <int A, bool FIRST>
__device__ __forceinline__ void addY(YA& y, const XP& x, const u64* W)
{
#pragma unroll
    for (int j = 0; j < 4; j++) {
        u64 t = FIRST ? mul2(W[3*A], x.P[2*j])
                      : fma2(W[3*A], x.P[2*j], y.a[j]);
        t = fma2(W[3*A+1], x.P[2*j+1], t);
        y.a[j] = fma2(W[3*A+2], x.P[2*j+2], t);
    }
    float e = FIRST ? (lo32(W[3*A]) * x.ea)
                    : fmaf(lo32(W[3*A]), x.ea, y.ae);
    e = fmaf(lo32(W[3*A+1]), x.eb, e);
    y.ae = fmaf(lo32(W[3*A+2]), x.ec, e);
}

template <bool SAFE>
__device__ __forceinline__ YQ fin(YA y, bool valid, bool killE, int lane)
{
    if (!SAFE && !valid) {
#pragma unroll
        for (int j = 0; j < 4; j++) y.a[j] = 0ull;
        y.ae = 0.f;
    }
    if (killE) y.ae = 0.f;
    float y0 = lo32(y.a[0]), y7 = hi32(y.a[3]);
    float up = __shfl_up_sync(0xffffffffu, y7, 1);
    float dn = __shfl_down_sync(0xffffffffu, y0, 1);
    float ym1 = (lane == 0)  ? y.ae : up;
    float yp8 = (lane == 31) ? y.ae : dn;
    YQ q;
    q.Q[0] = pk(ym1, y0);
#pragma unroll
    for (int j = 0; j < 4; j++) q.Q[2*j+1] = y.a[j];
#pragma unroll
    for (int j = 1; j < 4; j++) q.Q[2*j] = pk(hi32(y.a[j-1]), lo32(y.a[j]));
    q.Q[8] = pk(y7, yp8);
    return q;
}

template <int A, bool FIRST>
__device__ __forceinline__ void addZ(ZA& z, const YQ& q, const u64* W)
{
#pragma unroll
    for (int j = 0; j < 4; j++) {
        u64 t = FIRST ? mul2(W[3*A], q.Q[2*j])
                      : fma2(W[3*A], q.Q[2*j], z.a[j]);
        t = fma2(W[3*A+1], q.Q[2*j+1], t);
        z.a[j] = fma2(W[3*A+2], q.Q[2*j+2], t);
    }
}

__device__ __forceinline__ void stz(float* p, const ZA& z)
{
    *(float4*)p       = make_float4(lo32(z.a[0]), hi32(z.a[0]),
                                    lo32(z.a[1]), hi32(z.a[1]));
    *(float4*)(p + 4) = make_float4(lo32(z.a[2]), hi32(z.a[2]),
                                    lo32(z.a[3]), hi32(z.a[3]));
}

template <bool SAFE>
__device__ __forceinline__ void run(char* wb, uint32_t wb_u,
                                    const float* __restrict__ xb,
                                    float* __restrict__ ob,
                                    const float* __restrict__ w1g,
                                    const float* __restrict__ w2g,
                                    int c0, int R0, int lane, bool lE, bool rE)
{
    u64 W1[9], W2[9];
#pragma unroll
    for (int i = 0; i < 9; i++) {
        float a = __ldg(w1g + i); W1[i] = pk(a, a);
        float b = __ldg(w2g + i); W2[i] = pk(b, b);
    }
    const bool killE = (lane == 0 && lE) || (lane == 31 && rE);

    // Zero halo pads once; each pad is zeroed by the lane that later reads it.
    if (lane == 0) {
#pragma unroll
        for (int s = 0; s < RING; s++)
            *(float2*)(wb + s * ROWB + 24) = make_float2(0.f, 0.f);
    }
    if (lane == 31) {
#pragma unroll
        for (int s = 0; s < RING; s++)
            *(float2*)(wb + s * ROWB + 1056) = make_float2(0.f, 0.f);
    }

    // ---- Prologue: issue rows R0-2 .. R0+4 into slots 0..6 ----
    const float* srcp = xb + (size_t)(R0 - 2) * IMG_W + c0;
    int irow = R0 - 2;
#pragma unroll
    for (int s = 0; s < 7; s++) {
        issue_row<SAFE>(wb + s * ROWB, wb_u + s * ROWB, srcp, lane, lE, rE,
                        (unsigned)irow < IMG_H);
        asm volatile("cp.async.commit_group;");
        srcp += IMG_W; irow++;
    }

    int coff = 0;
    int ioff = 7 * ROWB;
    int nIssue = 61;            // rows R0+5 .. R0+65
    float* orow = ob + (size_t)R0 * IMG_W + c0 + 8 * lane;
    int r = R0;

#define CONSUME(XV)                                                           \
    do {                                                                      \
        asm volatile("cp.async.wait_group 6;");                               \
        XV = cvts(wb + coff, lane);                                           \
        coff += ROWB; if (coff == WSMEM) coff = 0;                            \
        if (nIssue > 0) {                                                     \
            issue_row<SAFE>(wb + ioff, wb_u + ioff, srcp, lane, lE, rE,       \
                            (unsigned)irow < IMG_H);                          \
            nIssue--; srcp += IMG_W; irow++;                                  \
            ioff += ROWB; if (ioff == WSMEM) ioff = 0;                        \
        }                                                                     \
        asm volatile("cp.async.commit_group;");                               \
    } while (0)

    YA t1, t2, ya, yb, yc;
    ZA za, zb, zc;

    XP A; CONSUME(A);                                  // row R0-2
    addY<0, true >(t1, A, W1);
    XP B; CONSUME(B);                                  // row R0-1
    addY<1, false>(t1, B, W1);
    addY<0, true >(t2, B, W1);
    XP C; CONSUME(C);                                  // row R0
    addY<2, false>(t1, C, W1);
    addY<1, false>(t2, C, W1);
    addY<0, true >(ya, C, W1);
    YQ Q = fin<SAFE>(t1, (unsigned)(R0 - 1) < IMG_H, killE, lane);
    addZ<0, true >(za, Q, W2);
    XP D; CONSUME(D);                                  // row R0+1
    addY<2, false>(t2, D, W1);
    addY<1, false>(ya, D, W1);
    addY<0, true >(yb, D, W1);
    Q = fin<SAFE>(t2, true, killE, lane);
    addZ<1, false>(za, Q, W2);
    addZ<0, true >(zb, Q, W2);

    XP X; CONSUME(X);                                  // row R0+2 (primes pipeline)

    // ---- Steady state: X = converted row r+2. addY first, then consume
    //      row r+3 (LDS overlaps fin/addZ), then finish and store z(r). ----
#define STEP(Y0, Y1, Y2, Z0, Z1, Z2)                                          \
    do {                                                                      \
        addY<2, false>(Y0, X, W1);                                            \
        addY<1, false>(Y1, X, W1);                                            \
        addY<0, true >(Y2, X, W1);                                            \
        XP Xn; CONSUME(Xn);                                                   \
        YQ Qs = fin<SAFE>(Y0, (unsigned)(r + 1) < IMG_H, killE, lane);        \
        addZ<2, false>(Z0, Qs, W2);                                           \
        addZ<1, false>(Z1, Qs, W2);                                           \
        addZ<0, true >(Z2, Qs, W2);                                           \
        stz(orow, Z0);                                                        \
        orow += IMG_W; r++;                                                   \
        X = Xn;                                                               \
    } while (0)

#define STEPNL(Y0, Y1, Y2, Z0, Z1, Z2)                                        \
    do {                                                                      \
        addY<2, false>(Y0, X, W1);                                            \
        addY<1, false>(Y1, X, W1);                                            \
        addY<0, true >(Y2, X, W1);                                            \
        YQ Qs = fin<SAFE>(Y0, (unsigned)(r + 1) < IMG_H, killE, lane);        \
        addZ<2, false>(Z0, Qs, W2);                                           \
        addZ<1, false>(Z1, Qs, W2);                                           \
        addZ<0, true >(Z2, Qs, W2);                                           \
        stz(orow, Z0);                                                        \
        orow += IMG_W; r++;                                                   \
    } while (0)

#pragma unroll 1
    for (int i = 0; i < 21; i++) {                     // 63 rows
        STEP(ya, yb, yc, za, zb, zc);
        STEP(yb, yc, ya, zb, zc, za);
        STEP(yc, ya, yb, zc, za, zb);
    }
    STEPNL(ya, yb, yc, za, zb, zc);                    // row 64 (X already held)
#undef STEP
#undef STEPNL
#undef CONSUME
}

__global__ __launch_bounds__(WARPS_PER_CTA * 32, 4)
void conv2x_ring4(const float* __restrict__ x, const float* __restrict__ w1g,
                  const float* __restrict__ w2g, float* __restrict__ out)
{
    __shared__ __align__(16) char smem[WARPS_PER_CTA * WSMEM];   // 34816 B

    const int lane  = threadIdx.x & 31;
    const int wrp   = threadIdx.x >> 5;
    const int strip = blockIdx.x;                       // 0..7
    const int chunk = blockIdx.y * WARPS_PER_CTA + wrp; // 0..31
    const int c0 = strip * 256;
    const int R0 = chunk * ROWS;
    const bool lE = (strip == 0);
    const bool rE = (strip == STRIPS - 1);

    char* wb = smem + wrp * WSMEM;
    uint32_t wb_u = (uint32_t)__cvta_generic_to_shared(wb);

    const float* xb = x   + (size_t)blockIdx.z * ((size_t)IMG_H * IMG_W);
    float*       ob = out + (size_t)blockIdx.z * ((size_t)IMG_H * IMG_W);

    if (chunk != 0 && chunk != (IMG_H / ROWS) - 1)
        run<true >(wb, wb_u, xb, ob, w1g, w2g, c0, R0, lane, lE, rE);
    else
        run<false>(wb, wb_u, xb, ob, w1g, w2g, c0, R0, lane, lE, rE);
}

extern "C" void kernel_launch(void* const* d_in, const int* in_sizes, int n_in,
                              void* d_out, int out_size)
{
    const float* x  = (const float*)d_in[0];
    const float* w1 = (const float*)d_in[1];
    const float* w2 = (const float*)d_in[2];
    float* out = (float*)d_out;

    // 4 CTAs/SM x 34.8 KB needs a large shared-memory carveout.
    cudaFuncSetAttribute(conv2x_ring4,
                         cudaFuncAttributePreferredSharedMemoryCarveout, 100);

    const int B = in_sizes[0] / (IMG_H * IMG_W);            // 16
    dim3 grid(STRIPS, (IMG_H / ROWS) / WARPS_PER_CTA, B);   // 8 x 8 x 16 = 1024
    conv2x_ring4<<<grid, WARPS_PER_CTA * 32>>>(x, w1, w2, out);
}

// round 15
// speedup vs baseline: 1.6290x; 1.0425x over previous
#include <cuda_runtime.h>
#include <cstdint>

// Fused y = conv3x3_same(x, w1); z = conv3x3_same(y, w2), [16,1,2048,2048] fp32.
// Round-12 structure (best) with the y-halo shuffles ELIMINATED: each lane
// computes its own (y[8g-1], y[8g+8]) pair locally as one extra f32x2 chain;
// the needed extra x values come from shuffles in cvts (a full step of slack).
// fin is now shuffle-free. Warp = 256-col strip x 64-row chunk, 8 cols/lane,
// warp-private 6-slot cp.async smem ring, ulonglong2 readback, LDS of row r+3
// overlapped with fin/addZ of z(r). y forced to 0 outside the image.

#define IMG_H 2048
#define IMG_W 2048
#define ROWS 64
#define STRIPS 8
#define WARPS_PER_CTA 4
#define RING 6
#define ROWB 1088                  // 8 pad + 256 data + 8 pad floats
#define WSMEM (RING * ROWB)

typedef unsigned long long u64;

__device__ __forceinline__ u64 pk(float lo, float hi) {
    u64 r; asm("mov.b64 %0, {%1, %2};" : "=l"(r) : "f"(lo), "f"(hi)); return r;
}
__device__ __forceinline__ float lo32(u64 v) { return __uint_as_float((unsigned)v); }
__device__ __forceinline__ float hi32(u64 v) { return __uint_as_float((unsigned)(v >> 32)); }
__device__ __forceinline__ u64 fma2(u64 a, u64 b, u64 c) {
    u64 d; asm("fma.rn.f32x2 %0, %1, %2, %3;" : "=l"(d) : "l"(a), "l"(b), "l"(c)); return d;
}
__device__ __forceinline__ u64 mul2(u64 a, u64 b) {
    u64 d; asm("mul.rn.f32x2 %0, %1, %2;" : "=l"(d) : "l"(a), "l"(b)); return d;
}
__device__ __forceinline__ void cpa16(uint32_t d, const float* s) {
    asm volatile("cp.async.cg.shared.global [%0], [%1], 16;" :: "r"(d), "l"(s));
}
__device__ __forceinline__ void cpa8(uint32_t d, const float* s) {
    asm volatile("cp.async.ca.shared.global [%0], [%1], 8;" :: "r"(d), "l"(s));
}

struct XP { u64 P[9]; u64 E[3]; };      // P[k]=(x[k-1],x[k]); E = edge-pair operands
struct YA { u64 a[4]; u64 e; };         // e accumulates (y[-1], y[8])
struct YQ { u64 Q[9]; };
struct ZA { u64 a[4]; };

template <bool SAFE>
__device__ __forceinline__ void issue_row(char* slot, uint32_t slot_u,
                                          const float* src, int lane,
                                          bool lE, bool rE, bool inimg)
{
    if (SAFE || inimg) {
        uint32_t d = slot_u + 32 + lane * 32;
        cpa16(d,      src + 8 * lane);
        cpa16(d + 16, src + 8 * lane + 4);
        if (lane == 0  && !lE) cpa8(slot_u + 24,   src - 2);     // x[-2],x[-1]
        if (lane == 31 && !rE) cpa8(slot_u + 1056, src + 256);   // x[256],x[257]
    } else {
        float4 z4 = make_float4(0.f, 0.f, 0.f, 0.f);
        *(float4*)(slot + 32 + lane * 32) = z4;
        *(float4*)(slot + 48 + lane * 32) = z4;
        if (lane == 0)  *(float2*)(slot + 24)   = make_float2(0.f, 0.f);
        if (lane == 31) *(float2*)(slot + 1056) = make_float2(0.f, 0.f);
    }
}

// Read a ready slot: 2x LDS.128 (aligned pairs free) + own halo + 4 shuffles.
// All shuffles are here (one full step before their results hit the critical
// fin->addZ->store path).
__device__ __forceinline__ XP cvts(const char* slot, int lane)
{
    const float* sf = (const float*)slot;
    const ulonglong2* dp = (const ulonglong2*)(sf + 8 + lane * 8);
    ulonglong2 A = dp[0], B = dp[1];
    float2 h = *(const float2*)(sf + ((lane == 31) ? 264 : 6));
    float v0 = lo32(A.x), v1 = hi32(A.x);
    float v6 = lo32(B.y), v7 = hi32(B.y);
    float up7 = __shfl_up_sync(0xffffffffu, v7, 1);
    float dn0 = __shfl_down_sync(0xffffffffu, v0, 1);
    float up6 = __shfl_up_sync(0xffffffffu, v6, 1);
    float dn1 = __shfl_down_sync(0xffffffffu, v1, 1);
    float xm1 = (lane == 0)  ? h.y : up7;   // x[8g-1]
    float xp8 = (lane == 31) ? h.x : dn0;   // x[8g+8]
    float xm2 = (lane == 0)  ? h.x : up6;   // x[8g-2]
    float xp9 = (lane == 31) ? h.y : dn1;   // x[8g+9]
    XP x;
    x.P[0] = pk(xm1, v0);
    x.P[1] = A.x;
    x.P[2] = pk(v1, lo32(A.y));
    x.P[3] = A.y;
    x.P[4] = pk(hi32(A.y), lo32(B.x));
    x.P[5] = B.x;
    x.P[6] = pk(hi32(B.x), v6);
    x.P[7] = B.y;
    x.P[8] = pk(v7, xp8);
    x.E[0] = pk(xm2, v7);                   // (x[-2], x[7])
    x.E[1] = pk(xm1, xp8);                  // (x[-1], x[8])
    x.E[2] = pk(v0,  xp9);                  // (x[0],  x[9])
    return x;
}

template <int A, bool FIRST>
__device__ __forceinline__ void addY(YA& y, const XP& x, const u64* W)
{
#pragma unroll
    for (int j = 0; j < 4; j++) {
        u64 t = FIRST ? mul2(W[3*A], x.P[2*j])
                      : fma2(W[3*A], x.P[2*j], y.a[j]);
        t = fma2(W[3*A+1], x.P[2*j+1], t);
        y.a[j] = fma2(W[3*A+2], x.P[2*j+2], t);
    }
    u64 e = FIRST ? mul2(W[3*A], x.E[0])
                  : fma2(W[3*A], x.E[0], y.e);
    e = fma2(W[3*A+1], x.E[1], e);
    y.e = fma2(W[3*A+2], x.E[2], e);
}

// Shuffle-free fin: halo y values are the lane-local pair y.e.
template <bool SAFE>
__device__ __forceinline__ YQ fin(YA y, bool valid, bool kL, bool kR)
{
    if (!SAFE && !valid) {
#pragma unroll
        for (int j = 0; j < 4; j++) y.a[j] = 0ull;
        y.e = 0ull;
    }
    float ym1 = lo32(y.e);
    float yp8 = hi32(y.e);
    if (kL) ym1 = 0.f;                 // lane 0 on left-edge strip
    if (kR) yp8 = 0.f;                 // lane 31 on right-edge strip
    YQ q;
    q.Q[0] = pk(ym1, lo32(y.a[0]));
#pragma unroll
    for (int j = 0; j < 4; j++) q.Q[2*j+1] = y.a[j];
#pragma unroll
    for (int j = 1; j < 4; j++) q.Q[2*j] = pk(hi32(y.a[j-1]), lo32(y.a[j]));
    q.Q[8] = pk(hi32(y.a[3]), yp8);
    return q;
}

template <int A, bool FIRST>
__device__ __forceinline__ void addZ(ZA& z, const YQ& q, const u64* W)
{
#pragma unroll
    for (int j = 0; j < 4; j++) {
        u64 t = FIRST ? mul2(W[3*A], q.Q[2*j])
                      : fma2(W[3*A], q.Q[2*j], z.a[j]);
        t = fma2(W[3*A+1], q.Q[2*j+1], t);
        z.a[j] = fma2(W[3*A+2], q.Q[2*j+2], t);
    }
}

__device__ __forceinline__ void stz(float* p, const ZA& z)
{
    *(float4*)p       = make_float4(lo32(z.a[0]), hi32(z.a[0]),
                                    lo32(z.a[1]), hi32(z.a[1]));
    *(float4*)(p + 4) = make_float4(lo32(z.a[2]), hi32(z.a[2]),
                                    lo32(z.a[3]), hi32(z.a[3]));
}

template <bool SAFE>
__device__ __forceinline__ void run(char* wb, uint32_t wb_u,
                                    const float* __restrict__ xb,
                                    float* __restrict__ ob,
                                    const float* __restrict__ w1g,
                                    const float* __restrict__ w2g,
                                    int c0, int R0, int lane, bool lE, bool rE)
{
    u64 W1[9], W2[9];
#pragma unroll
    for (int i = 0; i < 9; i++) {
        float a = __ldg(w1g + i); W1[i] = pk(a, a);
        float b = __ldg(w2g + i); W2[i] = pk(b, b);
    }
    const bool kL = (lane == 0  && lE);
    const bool kR = (lane == 31 && rE);

    // Zero halo pads once; each pad is zeroed by the lane that later reads it.
    if (lane == 0) {
#pragma unroll
        for (int s = 0; s < RING; s++)
            *(float2*)(wb + s * ROWB + 24) = make_float2(0.f, 0.f);
    }
    if (lane == 31) {
#pragma unroll
        for (int s = 0; s < RING; s++)
            *(float2*)(wb + s * ROWB + 1056) = make_float2(0.f, 0.f);
    }

    // ---- Prologue: issue rows R0-2 .. R0+2 into slots 0..4 ----
    const float* srcp = xb + (size_t)(R0 - 2) * IMG_W + c0;
    int irow = R0 - 2;
#pragma unroll
    for (int s = 0; s < 5; s++) {
        issue_row<SAFE>(wb + s * ROWB, wb_u + s * ROWB, srcp, lane, lE, rE,
                        (unsigned)irow < IMG_H);
        asm volatile("cp.async.commit_group;");
        srcp += IMG_W; irow++;
    }

    int coff = 0;
    int ioff = 5 * ROWB;
    int nIssue = 63;            // rows R0+3 .. R0+65
    float* orow = ob + (size_t)R0 * IMG_W + c0 + 8 * lane;
    int r = R0;

#define CONSUME(XV)                                                           \
    do {                                                                      \
        asm volatile("cp.async.wait_group 4;");                               \
        XV = cvts(wb + coff, lane);                                           \
        coff += ROWB; if (coff == WSMEM) coff = 0;                            \
        if (nIssue > 0) {                                                     \
            issue_row<SAFE>(wb + ioff, wb_u + ioff, srcp, lane, lE, rE,       \
                            (unsigned)irow < IMG_H);                          \
            nIssue--; srcp += IMG_W; irow++;                                  \
            ioff += ROWB; if (ioff == WSMEM) ioff = 0;                        \
        }                                                                     \
        asm volatile("cp.async.commit_group;");                               \
    } while (0)

    YA t1, t2, ya, yb, yc;
    ZA za, zb, zc;

    XP A; CONSUME(A);                                  // row R0-2
    addY<0, true >(t1, A, W1);
    XP B; CONSUME(B);                                  // row R0-1
    addY<1, false>(t1, B, W1);
    addY<0, true >(t2, B, W1);
    XP C; CONSUME(C);                                  // row R0
    addY<2, false>(t1, C, W1);
    addY<1, false>(t2, C, W1);
    addY<0, true >(ya, C, W1);
    YQ Q = fin<SAFE>(t1, (unsigned)(R0 - 1) < IMG_H, kL, kR);
    addZ<0, true >(za, Q, W2);
    XP D; CONSUME(D);                                  // row R0+1
    addY<2, false>(t2, D, W1);
    addY<1, false>(ya, D, W1);
    addY<0, true >(yb, D, W1);
    Q = fin<SAFE>(t2, true, kL, kR);
    addZ<1, false>(za, Q, W2);
    addZ<0, true >(zb, Q, W2);

    XP X; CONSUME(X);                                  // row R0+2 (primes pipeline)

    // ---- Steady state: X = converted row r+2. addY first, then consume
    //      row r+3 (LDS overlaps fin/addZ), then finish and store z(r). ----
#define STEP(Y0, Y1, Y2, Z0, Z1, Z2)                                          \
    do {                                                                      \
        addY<2, false>(Y0, X, W1);                                            \
        addY<1, false>(Y1, X, W1);                                            \
        addY<0, true >(Y2, X, W1);                                            \
        XP Xn; CONSUME(Xn);                                                   \
        YQ Qs = fin<SAFE>(Y0, (unsigned)(r + 1) < IMG_H, kL, kR);             \
        addZ<2, false>(Z0, Qs, W2);                                           \
        addZ<1, false>(Z1, Qs, W2);                                           \
        addZ<0, true >(Z2, Qs, W2);                                           \
        stz(orow, Z0);                                                        \
        orow += IMG_W; r++;                                                   \
        X = Xn;                                                               \
    } while (0)

#define STEPNL(Y0, Y1, Y2, Z0, Z1, Z2)                                        \
    do {                                                                      \
        addY<2, false>(Y0, X, W1);                                            \
        addY<1, false>(Y1, X, W1);                                            \
        addY<0, true >(Y2, X, W1);                                            \
        YQ Qs = fin<SAFE>(Y0, (unsigned)(r + 1) < IMG_H, kL, kR);             \
        addZ<2, false>(Z0, Qs, W2);                                           \
        addZ<1, false>(Z1, Qs, W2);                                           \
        addZ<0, true >(Z2, Qs, W2);                                           \
        stz(orow, Z0);                                                        \
        orow += IMG_W; r++;                                                   \
    } while (0)

#pragma unroll 1
    for (int i = 0; i < 21; i++) {                     // 63 rows
        STEP(ya, yb, yc, za, zb, zc);
        STEP(yb, yc, ya, zb, zc, za);
        STEP(yc, ya, yb, zc, za, zb);
    }
    STEPNL(ya, yb, yc, za, zb, zc);                    // row 64 (X already held)
#undef STEP
#undef STEPNL
#undef CONSUME
}

__global__ __launch_bounds__(WARPS_PER_CTA * 32, 4)
void conv2x_ring5(const float* __restrict__ x, const float* __restrict__ w1g,
                  const float* __restrict__ w2g, float* __restrict__ out)
{
    __shared__ __align__(16) char smem[WARPS_PER_CTA * WSMEM];   // 26112 B

    const int lane  = threadIdx.x & 31;
    const int wrp   = threadIdx.x >> 5;
    const int strip = blockIdx.x;                       // 0..7
    const int chunk = blockIdx.y * WARPS_PER_CTA + wrp; // 0..31
    const int c0 = strip * 256;
    const int R0 = chunk * ROWS;
    const bool lE = (strip == 0);
    const bool rE = (strip == STRIPS - 1);

    char* wb = smem + wrp * WSMEM;
    uint32_t wb_u = (uint32_t)__cvta_generic_to_shared(wb);

    const float* xb = x   + (size_t)blockIdx.z * ((size_t)IMG_H * IMG_W);
    float*       ob = out + (size_t)blockIdx.z * ((size_t)IMG_H * IMG_W);

    if (chunk != 0 && chunk != (IMG_H / ROWS) - 1)
        run<true >(wb, wb_u, xb, ob, w1g, w2g, c0, R0, lane, lE, rE);
    else
        run<false>(wb, wb_u, xb, ob, w1g, w2g, c0, R0, lane, lE, rE);
}

extern "C" void kernel_launch(void* const* d_in, const int* in_sizes, int n_in,
                              void* d_out, int out_size)
{
    const float* x  = (const float*)d_in[0];
    const float* w1 = (const float*)d_in[1];
    const float* w2 = (const float*)d_in[2];
    float* out = (float*)d_out;

    cudaFuncSetAttribute(conv2x_ring5,
                         cudaFuncAttributePreferredSharedMemoryCarveout, 100);

    const int B = in_sizes[0] / (IMG_H * IMG_W);            // 16
    dim3 grid(STRIPS, (IMG_H / ROWS) / WARPS_PER_CTA, B);   // 8 x 8 x 16 = 1024
    conv2x_ring5<<<grid, WARPS_PER_CTA * 32>>>(x, w1, w2, out);
}